// round 7
// baseline (speedup 1.0000x reference)
#include <cuda_runtime.h>
#include <cstdint>

// Problem dims
#define NB 32
#define C  64
#define H  128
#define W  128
#define CO 64
#define HO 64
#define WO 64

// Scratch: packed sign bits.
__device__ uint64_t g_xpack[NB * H * W];          // 4 MiB
__device__ uint64_t g_wpack[CO * 9];

// ---------------------------------------------------------------------------
// Kernel 1: pack x AND w sign bits. Blocks 0..1023 pack x (2 px/thread);
// block 1024 packs w (runs concurrently, latency hidden under x-pack).
// ---------------------------------------------------------------------------
__global__ __launch_bounds__(256) void pack_kernel(const float* __restrict__ x,
                                                   const float* __restrict__ w) {
    if (blockIdx.x == 1024) {
        for (int t = threadIdx.x; t < CO * 9; t += 256) {
            int co = t / 9;
            int k  = t - co * 9;
            uint32_t lo = 0, hi = 0;
            #pragma unroll 8
            for (int ci = 0; ci < 32; ++ci)
                lo |= (uint32_t)(w[(size_t)(co * 64 + ci) * 9 + k] >= 0.0f) << ci;
            #pragma unroll 8
            for (int ci = 0; ci < 32; ++ci)
                hi |= (uint32_t)(w[(size_t)(co * 64 + ci + 32) * 9 + k] >= 0.0f) << ci;
            g_wpack[t] = (uint64_t)lo | ((uint64_t)hi << 32);
        }
        return;
    }

    int tid = blockIdx.x * blockDim.x + threadIdx.x;   // 0 .. 262143
    int w2 = tid & 63;
    int h  = (tid >> 6) & 127;
    int n  = tid >> 13;

    const float* base = x + (size_t)n * C * (H * W) + h * W + w2 * 2;

    uint32_t lo0 = 0, lo1 = 0, hi0 = 0, hi1 = 0;

    #pragma unroll 16
    for (int c = 0; c < 32; ++c) {
        float2 v = *reinterpret_cast<const float2*>(base + (size_t)c * (H * W));
        lo0 |= (uint32_t)(v.x >= 0.0f) << c;
        lo1 |= (uint32_t)(v.y >= 0.0f) << c;
    }
    #pragma unroll 16
    for (int c = 0; c < 32; ++c) {
        float2 v = *reinterpret_cast<const float2*>(base + (size_t)(c + 32) * (H * W));
        hi0 |= (uint32_t)(v.x >= 0.0f) << c;
        hi1 |= (uint32_t)(v.y >= 0.0f) << c;
    }

    uint64_t* op = g_xpack + ((size_t)n * H + h) * W + w2 * 2;
    op[0] = (uint64_t)lo0 | ((uint64_t)hi0 << 32);
    op[1] = (uint64_t)lo1 | ((uint64_t)hi1 << 32);
}

// ---------------------------------------------------------------------------
// Kernel 2: XNOR-popcount conv, direct form (CSA reverted — POPC is
// full-rate on the alu pipe, so direct 18 LOP3 + 18 POPC is minimal).
// Weight rows padded to 10 words (80 B, 16 B-aligned) so each c_out's
// 9 taps load as 4x LDS.128 + 1x LDS.64 instead of 9x LDS.64.
// Grid: (16 ho-groups, NB, 2 co-halves), 256 threads: tx=wo, ty=local ho.
// ---------------------------------------------------------------------------
__global__ __launch_bounds__(256) void qconv_kernel(float* __restrict__ out) {
    const int PW = 132;
    __shared__ __align__(16) uint64_t sw[32 * 10];   // padded weight rows
    __shared__ uint64_t sp[9 * 132];

    int n   = blockIdx.y;
    int ho0 = blockIdx.x * 4;
    int coh = blockIdx.z * 32;
    int iy0 = 2 * ho0 - 1;

    for (int i = threadIdx.x; i < 9 * 129; i += 256) {
        int r  = i / 129;
        int cx = i - r * 129;
        int iy = iy0 + r;
        int ix = cx - 1;
        uint64_t v = 0;
        if (iy >= 0 && ix >= 0)
            v = g_xpack[((size_t)n * H + iy) * W + ix];
        sp[r * PW + cx] = v;
    }
    // Stage weights into padded rows: sw[co*10 + t], t<9
    for (int i = threadIdx.x; i < 32 * 9; i += 256) {
        int co = i / 9;
        int t  = i - co * 9;
        sw[co * 10 + t] = g_wpack[(coh + co) * 9 + t];
    }
    __syncthreads();

    int tx = threadIdx.x & 63;    // wo
    int ty = threadIdx.x >> 6;    // local ho
    int ho = ho0 + ty;

    uint32_t slo[9], shi[9], msk[9];
    #pragma unroll
    for (int ky = 0; ky < 3; ++ky) {
        #pragma unroll
        for (int kx = 0; kx < 3; ++kx) {
            int t = ky * 3 + kx;
            uint64_t s = sp[(2 * ty + ky) * PW + 2 * tx + kx];
            slo[t] = (uint32_t)s;
            shi[t] = (uint32_t)(s >> 32);
            bool valid = (ho > 0 || ky > 0) && (tx > 0 || kx > 0);
            msk[t] = valid ? 0xFFFFFFFFu : 0u;
        }
    }
    int nvalid = (ho > 0 ? 3 : 2) * (tx > 0 ? 3 : 2);
    int base   = 64 * nvalid;

    float* op = out + (((size_t)n * CO + coh) * HO + ho) * WO + tx;

    #pragma unroll 4
    for (int co = 0; co < 32; ++co) {
        // 4x LDS.128 + 1x LDS.64 (warp-uniform broadcast)
        const uint4* wq = reinterpret_cast<const uint4*>(sw + co * 10);
        uint4 q0 = wq[0];   // taps 0,1  (lo0,hi0,lo1,hi1)
        uint4 q1 = wq[1];   // taps 2,3
        uint4 q2 = wq[2];   // taps 4,5
        uint4 q3 = wq[3];   // taps 6,7
        uint64_t w8 = sw[co * 10 + 8];

        uint32_t wlo[9], whi[9];
        wlo[0] = q0.x; whi[0] = q0.y; wlo[1] = q0.z; whi[1] = q0.w;
        wlo[2] = q1.x; whi[2] = q1.y; wlo[3] = q1.z; whi[3] = q1.w;
        wlo[4] = q2.x; whi[4] = q2.y; wlo[5] = q2.z; whi[5] = q2.w;
        wlo[6] = q3.x; whi[6] = q3.y; wlo[7] = q3.z; whi[7] = q3.w;
        wlo[8] = (uint32_t)w8; whi[8] = (uint32_t)(w8 >> 32);

        int acc = 0;
        #pragma unroll
        for (int t = 0; t < 9; ++t) {
            acc += __popc((slo[t] ^ wlo[t]) & msk[t]);
            acc += __popc((shi[t] ^ whi[t]) & msk[t]);
        }
        op[(size_t)co * (HO * WO)] = (float)(base - 2 * acc);
    }
}

// ---------------------------------------------------------------------------
extern "C" void kernel_launch(void* const* d_in, const int* in_sizes, int n_in,
                              void* d_out, int out_size) {
    const float* x = (const float*)d_in[0];
    const float* w = (const float*)d_in[1];
    float* out = (float*)d_out;

    pack_kernel<<<1025, 256>>>(x, w);
    qconv_kernel<<<dim3(16, NB, 2), 256>>>(out);
}

// round 8
// speedup vs baseline: 1.0529x; 1.0529x over previous
#include <cuda_runtime.h>
#include <cstdint>

// Problem dims
#define NB 32
#define C  64
#define H  128
#define W  128
#define CO 64
#define HO 64
#define WO 64

// Scratch: packed sign bits.
__device__ uint64_t g_xpack[NB * H * W];          // 4 MiB
__device__ uint64_t g_wpack[CO * 9];

// ---------------------------------------------------------------------------
// Kernel 1: pack x AND w sign bits. Blocks 0..1023 pack x (2 px/thread,
// streaming __ldcs loads); block 1024 packs w (latency hidden under x-pack).
// ---------------------------------------------------------------------------
__global__ __launch_bounds__(256) void pack_kernel(const float* __restrict__ x,
                                                   const float* __restrict__ w) {
    if (blockIdx.x == 1024) {
        for (int t = threadIdx.x; t < CO * 9; t += 256) {
            int co = t / 9;
            int k  = t - co * 9;
            uint32_t lo = 0, hi = 0;
            #pragma unroll 8
            for (int ci = 0; ci < 32; ++ci)
                lo |= (uint32_t)(w[(size_t)(co * 64 + ci) * 9 + k] >= 0.0f) << ci;
            #pragma unroll 8
            for (int ci = 0; ci < 32; ++ci)
                hi |= (uint32_t)(w[(size_t)(co * 64 + ci + 32) * 9 + k] >= 0.0f) << ci;
            g_wpack[t] = (uint64_t)lo | ((uint64_t)hi << 32);
        }
        return;
    }

    int tid = blockIdx.x * blockDim.x + threadIdx.x;   // 0 .. 262143
    int w2 = tid & 63;
    int h  = (tid >> 6) & 127;
    int n  = tid >> 13;

    const float* base = x + (size_t)n * C * (H * W) + h * W + w2 * 2;

    uint32_t lo0 = 0, lo1 = 0, hi0 = 0, hi1 = 0;

    #pragma unroll 16
    for (int c = 0; c < 32; ++c) {
        float2 v = __ldcs(reinterpret_cast<const float2*>(base + (size_t)c * (H * W)));
        lo0 |= (uint32_t)(v.x >= 0.0f) << c;
        lo1 |= (uint32_t)(v.y >= 0.0f) << c;
    }
    #pragma unroll 16
    for (int c = 0; c < 32; ++c) {
        float2 v = __ldcs(reinterpret_cast<const float2*>(base + (size_t)(c + 32) * (H * W)));
        hi0 |= (uint32_t)(v.x >= 0.0f) << c;
        hi1 |= (uint32_t)(v.y >= 0.0f) << c;
    }

    uint64_t* op = g_xpack + ((size_t)n * H + h) * W + w2 * 2;
    op[0] = (uint64_t)lo0 | ((uint64_t)hi0 << 32);
    op[1] = (uint64_t)lo1 | ((uint64_t)hi1 << 32);
}

// ---------------------------------------------------------------------------
// Kernel 2: XNOR-popcount conv, direct form, 2 output pixels per thread.
// Block = 128 threads: tx = wo (0..63), ty = 0..1. Thread computes rows
// ho0+ty and ho0+ty+2 — both pairs live inside the same 9-row input patch,
// so the 9 weight LDS per c_out are amortized over 72 LOP3/POPC (2x density
// vs 1 pixel). Grid (16, NB, 2) = 1024 blocks of 128 thr -> ~7 blocks/SM,
// balanced wave.
// out[n][co][ho][wo] = 64*nvalid - 2 * sum_t popc((s_t ^ wb_t) & m_t)
// ---------------------------------------------------------------------------
__global__ __launch_bounds__(128) void qconv_kernel(float* __restrict__ out) {
    const int PW = 132;
    __shared__ uint64_t sw[32 * 9];
    __shared__ uint64_t sp[9 * 132];

    int n   = blockIdx.y;
    int ho0 = blockIdx.x * 4;
    int coh = blockIdx.z * 32;
    int iy0 = 2 * ho0 - 1;

    for (int i = threadIdx.x; i < 9 * 129; i += 128) {
        int r  = i / 129;
        int cx = i - r * 129;
        int iy = iy0 + r;
        int ix = cx - 1;
        uint64_t v = 0;
        if (iy >= 0 && ix >= 0)
            v = g_xpack[((size_t)n * H + iy) * W + ix];
        sp[r * PW + cx] = v;
    }
    for (int i = threadIdx.x; i < 32 * 9; i += 128)
        sw[i] = g_wpack[coh * 9 + i];
    __syncthreads();

    int tx  = threadIdx.x & 63;    // wo
    int ty  = threadIdx.x >> 6;    // 0..1
    int hoA = ho0 + ty;            // pixel A row
    // pixel B row = hoA + 2 (always >= 2, so its rows are never clipped)

    uint32_t sAlo[9], sAhi[9], sBlo[9], sBhi[9], mA[9], mB[9];
    #pragma unroll
    for (int ky = 0; ky < 3; ++ky) {
        #pragma unroll
        for (int kx = 0; kx < 3; ++kx) {
            int t = ky * 3 + kx;
            uint64_t a = sp[(2 * ty + ky)     * PW + 2 * tx + kx];
            uint64_t b = sp[(2 * ty + 4 + ky) * PW + 2 * tx + kx];
            sAlo[t] = (uint32_t)a;  sAhi[t] = (uint32_t)(a >> 32);
            sBlo[t] = (uint32_t)b;  sBhi[t] = (uint32_t)(b >> 32);
            bool colv = (tx > 0 || kx > 0);
            mA[t] = ((hoA > 0 || ky > 0) && colv) ? 0xFFFFFFFFu : 0u;
            mB[t] = colv ? 0xFFFFFFFFu : 0u;
        }
    }
    int cw    = (tx > 0 ? 3 : 2);
    int baseA = 64 * (hoA > 0 ? 3 : 2) * cw;
    int baseB = 64 * 3 * cw;

    float* opA = out + (((size_t)n * CO + coh) * HO + hoA) * WO + tx;
    float* opB = opA + 2 * WO;

    #pragma unroll 2
    for (int co = 0; co < 32; ++co) {
        const uint64_t* wrow = sw + co * 9;
        int accA = 0, accB = 0;
        #pragma unroll
        for (int t = 0; t < 9; ++t) {
            uint64_t wv = wrow[t];                  // warp-uniform broadcast LDS
            uint32_t wl = (uint32_t)wv;
            uint32_t wh = (uint32_t)(wv >> 32);
            accA += __popc((sAlo[t] ^ wl) & mA[t]);
            accA += __popc((sAhi[t] ^ wh) & mA[t]);
            accB += __popc((sBlo[t] ^ wl) & mB[t]);
            accB += __popc((sBhi[t] ^ wh) & mB[t]);
        }
        size_t off = (size_t)co * (HO * WO);
        opA[off] = (float)(baseA - 2 * accA);
        opB[off] = (float)(baseB - 2 * accB);
    }
}

// ---------------------------------------------------------------------------
extern "C" void kernel_launch(void* const* d_in, const int* in_sizes, int n_in,
                              void* d_out, int out_size) {
    const float* x = (const float*)d_in[0];
    const float* w = (const float*)d_in[1];
    float* out = (float*)d_out;

    pack_kernel<<<1025, 256>>>(x, w);
    qconv_kernel<<<dim3(16, NB, 2), 128>>>(out);
}

// round 9
// speedup vs baseline: 1.1563x; 1.0981x over previous
#include <cuda_runtime.h>
#include <cstdint>

// Problem dims
#define NB 32
#define C  64
#define H  128
#define W  128
#define CO 64
#define HO 64
#define WO 64

// Scratch: packed sign bits.
__device__ uint64_t g_xpack[NB * H * W];          // 4 MiB
__device__ uint64_t g_wpack[CO * 9];

// ---------------------------------------------------------------------------
// Kernel 1: pack x AND w sign bits.
// Blocks 0..1023: pack x, 2 px/thread, streaming __ldcs loads.
// Blocks 1024..1039: pack w, 36 (co,tap) words per block — spread so the
// w-pack finishes well inside pack_x's shadow (was a ~8us single-block
// straggler before).
// ---------------------------------------------------------------------------
__global__ __launch_bounds__(256) void pack_kernel(const float* __restrict__ x,
                                                   const float* __restrict__ w) {
    if (blockIdx.x >= 1024) {
        int t = (blockIdx.x - 1024) * 36 + threadIdx.x;
        if (threadIdx.x < 36 && t < CO * 9) {
            int co = t / 9;
            int k  = t - co * 9;
            uint32_t lo = 0, hi = 0;
            #pragma unroll 8
            for (int ci = 0; ci < 32; ++ci)
                lo |= (uint32_t)(w[(size_t)(co * 64 + ci) * 9 + k] >= 0.0f) << ci;
            #pragma unroll 8
            for (int ci = 0; ci < 32; ++ci)
                hi |= (uint32_t)(w[(size_t)(co * 64 + ci + 32) * 9 + k] >= 0.0f) << ci;
            g_wpack[t] = (uint64_t)lo | ((uint64_t)hi << 32);
        }
        return;
    }

    int tid = blockIdx.x * blockDim.x + threadIdx.x;   // 0 .. 262143
    int w2 = tid & 63;
    int h  = (tid >> 6) & 127;
    int n  = tid >> 13;

    const float* base = x + (size_t)n * C * (H * W) + h * W + w2 * 2;

    uint32_t lo0 = 0, lo1 = 0, hi0 = 0, hi1 = 0;

    #pragma unroll 16
    for (int c = 0; c < 32; ++c) {
        float2 v = __ldcs(reinterpret_cast<const float2*>(base + (size_t)c * (H * W)));
        lo0 |= (uint32_t)(v.x >= 0.0f) << c;
        lo1 |= (uint32_t)(v.y >= 0.0f) << c;
    }
    #pragma unroll 16
    for (int c = 0; c < 32; ++c) {
        float2 v = __ldcs(reinterpret_cast<const float2*>(base + (size_t)(c + 32) * (H * W)));
        hi0 |= (uint32_t)(v.x >= 0.0f) << c;
        hi1 |= (uint32_t)(v.y >= 0.0f) << c;
    }

    uint64_t* op = g_xpack + ((size_t)n * H + h) * W + w2 * 2;
    op[0] = (uint64_t)lo0 | ((uint64_t)hi0 << 32);
    op[1] = (uint64_t)lo1 | ((uint64_t)hi1 << 32);
}

// ---------------------------------------------------------------------------
// Kernel 2: XNOR-popcount conv, direct form, 1 pixel/thread (best measured
// config). Only 3 distinct boundary masks exist (row, col, row&col); taps
// 4,5,7,8 are never clipped -> plain XOR. Keeps registers low so ptxas can
// schedule the 18 LOP3 + 18 POPC chain densely at unroll 4.
// Grid: (16 ho-groups, NB, 2 co-halves), 256 threads: tx=wo, ty=local ho.
// ---------------------------------------------------------------------------
__global__ __launch_bounds__(256) void qconv_kernel(float* __restrict__ out) {
    const int PW = 132;
    __shared__ uint64_t sw[32 * 9];
    __shared__ uint64_t sp[9 * 132];

    int n   = blockIdx.y;
    int ho0 = blockIdx.x * 4;
    int coh = blockIdx.z * 32;
    int iy0 = 2 * ho0 - 1;

    for (int i = threadIdx.x; i < 9 * 129; i += 256) {
        int r  = i / 129;
        int cx = i - r * 129;
        int iy = iy0 + r;
        int ix = cx - 1;
        uint64_t v = 0;
        if (iy >= 0 && ix >= 0)
            v = g_xpack[((size_t)n * H + iy) * W + ix];
        sp[r * PW + cx] = v;
    }
    for (int i = threadIdx.x; i < 32 * 9; i += 256)
        sw[i] = g_wpack[coh * 9 + i];
    __syncthreads();

    int tx = threadIdx.x & 63;    // wo
    int ty = threadIdx.x >> 6;    // local ho
    int ho = ho0 + ty;

    uint32_t slo[9], shi[9];
    #pragma unroll
    for (int ky = 0; ky < 3; ++ky) {
        #pragma unroll
        for (int kx = 0; kx < 3; ++kx) {
            int t = ky * 3 + kx;
            uint64_t s = sp[(2 * ty + ky) * PW + 2 * tx + kx];
            slo[t] = (uint32_t)s;
            shi[t] = (uint32_t)(s >> 32);
        }
    }
    uint32_t mr = (ho > 0) ? 0xFFFFFFFFu : 0u;   // ky==0 taps
    uint32_t mc = (tx > 0) ? 0xFFFFFFFFu : 0u;   // kx==0 taps
    uint32_t mb = mr & mc;                        // tap 0
    int nvalid = (ho > 0 ? 3 : 2) * (tx > 0 ? 3 : 2);
    int base   = 64 * nvalid;

    float* op = out + (((size_t)n * CO + coh) * HO + ho) * WO + tx;

    #pragma unroll 4
    for (int co = 0; co < 32; ++co) {
        const uint64_t* wrow = sw + co * 9;
        int acc = 0;
        #pragma unroll
        for (int t = 0; t < 9; ++t) {
            uint64_t wv = wrow[t];                  // warp-uniform broadcast LDS
            uint32_t wl = (uint32_t)wv;
            uint32_t wh = (uint32_t)(wv >> 32);
            if (t == 0) {
                acc += __popc((slo[t] ^ wl) & mb);
                acc += __popc((shi[t] ^ wh) & mb);
            } else if (t == 1 || t == 2) {
                acc += __popc((slo[t] ^ wl) & mr);
                acc += __popc((shi[t] ^ wh) & mr);
            } else if (t == 3 || t == 6) {
                acc += __popc((slo[t] ^ wl) & mc);
                acc += __popc((shi[t] ^ wh) & mc);
            } else {
                acc += __popc(slo[t] ^ wl);
                acc += __popc(shi[t] ^ wh);
            }
        }
        op[(size_t)co * (HO * WO)] = (float)(base - 2 * acc);
    }
}

// ---------------------------------------------------------------------------
extern "C" void kernel_launch(void* const* d_in, const int* in_sizes, int n_in,
                              void* d_out, int out_size) {
    const float* x = (const float*)d_in[0];
    const float* w = (const float*)d_in[1];
    float* out = (float*)d_out;

    pack_kernel<<<1040, 256>>>(x, w);
    qconv_kernel<<<dim3(16, NB, 2), 256>>>(out);
}

// round 10
// speedup vs baseline: 1.1929x; 1.0317x over previous
#include <cuda_runtime.h>
#include <cstdint>

// Problem dims
#define NB 32
#define C  64
#define H  128
#define W  128
#define CO 64
#define HO 64
#define WO 64

// Packed weight sign bits: g_wpack[co*9 + ky*3 + kx]
__device__ uint64_t g_wpack[CO * 9];

// ---------------------------------------------------------------------------
// Kernel 1: pack w sign bits (tiny; 16 blocks x 36 words).
// ---------------------------------------------------------------------------
__global__ __launch_bounds__(64) void pack_w_kernel(const float* __restrict__ w) {
    int t = blockIdx.x * 36 + threadIdx.x;
    if (threadIdx.x < 36 && t < CO * 9) {
        int co = t / 9;
        int k  = t - co * 9;
        uint32_t lo = 0, hi = 0;
        #pragma unroll 8
        for (int ci = 0; ci < 32; ++ci)
            lo |= (uint32_t)(w[(size_t)(co * 64 + ci) * 9 + k] >= 0.0f) << ci;
        #pragma unroll 8
        for (int ci = 0; ci < 32; ++ci)
            hi |= (uint32_t)(w[(size_t)(co * 64 + ci + 32) * 9 + k] >= 0.0f) << ci;
        g_wpack[t] = (uint64_t)lo | ((uint64_t)hi << 32);
    }
}

// ---------------------------------------------------------------------------
// Kernel 2: FUSED pack-x + XNOR-popcount conv.
// Grid (32 ho-groups, NB): block computes 2 output rows x 64 wo x ALL 64 co.
// Phase 1: pack the 5-row x 129-word input patch straight from x floats into
//          smem (no global xpack roundtrip). Lanes take consecutive ix ->
//          coalesced 128B lines per channel; 64-ch reduction, 2 inst/ch.
// Phase 2: R9's proven compute loop. 256 threads = 2 rows x 64 wo x
//          2 co-halves; each thread: 1 pixel, 32 c_out.
// The HBM streaming of phase 1 (1.25x x traffic ~= 168MB ~= 30us) hides under
// the ~44us of ALU compute across the ~6 resident blocks per SM.
// ---------------------------------------------------------------------------
__global__ __launch_bounds__(256) void qconv_fused_kernel(const float* __restrict__ x,
                                                          float* __restrict__ out) {
    const int PW = 132;
    __shared__ uint64_t sw[CO * 9];        // 4608 B
    __shared__ uint64_t sp[5 * PW];        // 5280 B

    int n   = blockIdx.y;
    int ho0 = blockIdx.x * 2;              // 2 output rows per block
    int iy0 = 2 * ho0 - 1;                 // first patch row

    // ---- Phase 1a: pack input patch (5 rows x 129 words) from x ----
    for (int i = threadIdx.x; i < 5 * 129; i += 256) {
        int r  = i / 129;
        int cx = i - r * 129;
        int iy = iy0 + r;
        int ix = cx - 1;
        uint32_t lo = 0, hi = 0;
        if (iy >= 0 && ix >= 0) {          // upper bounds always in range
            const float* p = x + (size_t)n * C * (H * W) + iy * W + ix;
            #pragma unroll 16
            for (int c = 0; c < 32; ++c) {
                lo |= (uint32_t)(__ldcs(p + (size_t)c * (H * W)) >= 0.0f) << c;
                hi |= (uint32_t)(__ldcs(p + (size_t)(c + 32) * (H * W)) >= 0.0f) << c;
            }
        }
        sp[r * PW + cx] = (uint64_t)lo | ((uint64_t)hi << 32);
    }
    // ---- Phase 1b: stage all 64 co weight rows ----
    for (int i = threadIdx.x; i < CO * 9; i += 256)
        sw[i] = g_wpack[i];
    __syncthreads();

    // ---- Phase 2: compute ----
    int tx  = threadIdx.x & 63;            // wo
    int ty  = threadIdx.x >> 6;            // 0..3
    int q   = ty & 1;                      // row within group
    int coh = (ty >> 1) * 32;              // co half
    int ho  = ho0 + q;

    uint32_t slo[9], shi[9];
    #pragma unroll
    for (int ky = 0; ky < 3; ++ky) {
        #pragma unroll
        for (int kx = 0; kx < 3; ++kx) {
            int t = ky * 3 + kx;
            uint64_t s = sp[(2 * q + ky) * PW + 2 * tx + kx];
            slo[t] = (uint32_t)s;
            shi[t] = (uint32_t)(s >> 32);
        }
    }
    uint32_t mr = (ho > 0) ? 0xFFFFFFFFu : 0u;   // ky==0 taps
    uint32_t mc = (tx > 0) ? 0xFFFFFFFFu : 0u;   // kx==0 taps
    uint32_t mb = mr & mc;                        // tap 0
    int nvalid = (ho > 0 ? 3 : 2) * (tx > 0 ? 3 : 2);
    int base   = 64 * nvalid;

    float* op = out + (((size_t)n * CO + coh) * HO + ho) * WO + tx;
    const uint64_t* wbase = sw + coh * 9;

    #pragma unroll 4
    for (int co = 0; co < 32; ++co) {
        const uint64_t* wrow = wbase + co * 9;
        int acc = 0;
        #pragma unroll
        for (int t = 0; t < 9; ++t) {
            uint64_t wv = wrow[t];                // warp-uniform broadcast LDS
            uint32_t wl = (uint32_t)wv;
            uint32_t wh = (uint32_t)(wv >> 32);
            if (t == 0) {
                acc += __popc((slo[t] ^ wl) & mb);
                acc += __popc((shi[t] ^ wh) & mb);
            } else if (t == 1 || t == 2) {
                acc += __popc((slo[t] ^ wl) & mr);
                acc += __popc((shi[t] ^ wh) & mr);
            } else if (t == 3 || t == 6) {
                acc += __popc((slo[t] ^ wl) & mc);
                acc += __popc((shi[t] ^ wh) & mc);
            } else {
                acc += __popc(slo[t] ^ wl);
                acc += __popc(shi[t] ^ wh);
            }
        }
        op[(size_t)co * (HO * WO)] = (float)(base - 2 * acc);
    }
}

// ---------------------------------------------------------------------------
extern "C" void kernel_launch(void* const* d_in, const int* in_sizes, int n_in,
                              void* d_out, int out_size) {
    const float* x = (const float*)d_in[0];
    const float* w = (const float*)d_in[1];
    float* out = (float*)d_out;

    pack_w_kernel<<<16, 64>>>(w);
    qconv_fused_kernel<<<dim3(32, NB), 256>>>(x, out);
}